// round 5
// baseline (speedup 1.0000x reference)
#include <cuda_runtime.h>

// Problem constants (fixed by the dataset)
#define NE    1024          // n_embd
#define H     128           // head_size
#define B_MAX 16384

// Scratch for GEMM outputs (device globals: no allocation allowed)
__device__ float g_values[B_MAX * H];
__device__ float g_mask[B_MAX * H];

// ---------------------------------------------------------------------------
// Kernel A: dual GEMM.  rows = 2*B, out[row,h] = dot(x[row,:], W[h,:])
// row = 2*b + s : s==0 -> values, s==1 -> mask.
// Tile: BM=64 rows x BN=128 cols x BK=16, 256 threads, f32x2 packed FMA.
// ---------------------------------------------------------------------------
#define BM 64
#define BN 128
#define BK 16

__global__ __launch_bounds__(256, 2)
void gemm_vm_kernel(const float* __restrict__ x, const float* __restrict__ W)
{
    __shared__ float xs[BK][BM];   // xs[kk][m]
    __shared__ float ws[BK][BN];   // ws[kk][h]

    const int tid  = threadIdx.x;
    const int tx   = tid & 31;     // n-group: cols tx*4 .. tx*4+3
    const int ty   = tid >> 5;     // m-group: rows ty*8 .. ty*8+7
    const int row0 = blockIdx.x * BM;

    // loader mapping (same for x and W loaders)
    const int lrow = tid >> 2;     // 0..63
    const int lkq  = tid & 3;      // float4 index within 16-wide k tile
    const int h0l  = lrow;         // 0..63
    const int h1l  = lrow + 64;    // 64..127

    unsigned long long acc0[8], acc1[8];
#pragma unroll
    for (int i = 0; i < 8; i++) { acc0[i] = 0ull; acc1[i] = 0ull; }

    // prefetch tile 0 into registers
    float4 xv  = *(const float4*)(x + (size_t)(row0 + lrow) * NE + lkq * 4);
    float4 wv0 = *(const float4*)(W + (size_t)h0l * NE + lkq * 4);
    float4 wv1 = *(const float4*)(W + (size_t)h1l * NE + lkq * 4);

    for (int kt = 0; kt < NE / BK; kt++) {
        __syncthreads();   // previous compute done -> smem reusable
        xs[lkq*4+0][lrow] = xv.x;  xs[lkq*4+1][lrow] = xv.y;
        xs[lkq*4+2][lrow] = xv.z;  xs[lkq*4+3][lrow] = xv.w;
        ws[lkq*4+0][h0l]  = wv0.x; ws[lkq*4+1][h0l]  = wv0.y;
        ws[lkq*4+2][h0l]  = wv0.z; ws[lkq*4+3][h0l]  = wv0.w;
        ws[lkq*4+0][h1l]  = wv1.x; ws[lkq*4+1][h1l]  = wv1.y;
        ws[lkq*4+2][h1l]  = wv1.z; ws[lkq*4+3][h1l]  = wv1.w;
        __syncthreads();

        // prefetch next tile (LDG latency hidden under the FFMA2 block below)
        if (kt + 1 < NE / BK) {
            const int ko = (kt + 1) * BK;
            xv  = *(const float4*)(x + (size_t)(row0 + lrow) * NE + ko + lkq * 4);
            wv0 = *(const float4*)(W + (size_t)h0l * NE + ko + lkq * 4);
            wv1 = *(const float4*)(W + (size_t)h1l * NE + ko + lkq * 4);
        }

#pragma unroll
        for (int kk = 0; kk < BK; kk++) {
            float4 wq = *(const float4*)&ws[kk][tx * 4];
            unsigned long long wp0, wp1;
            asm("mov.b64 %0, {%1,%2};" : "=l"(wp0) : "f"(wq.x), "f"(wq.y));
            asm("mov.b64 %0, {%1,%2};" : "=l"(wp1) : "f"(wq.z), "f"(wq.w));
            float4 xa = *(const float4*)&xs[kk][ty * 8];       // broadcast
            float4 xb = *(const float4*)&xs[kk][ty * 8 + 4];   // broadcast
            float xm[8] = {xa.x, xa.y, xa.z, xa.w, xb.x, xb.y, xb.z, xb.w};
#pragma unroll
            for (int i = 0; i < 8; i++) {
                unsigned long long xp;
                asm("mov.b64 %0, {%1,%1};" : "=l"(xp) : "f"(xm[i]));
                asm("fma.rn.f32x2 %0, %1, %2, %0;" : "+l"(acc0[i]) : "l"(xp), "l"(wp0));
                asm("fma.rn.f32x2 %0, %1, %2, %0;" : "+l"(acc1[i]) : "l"(xp), "l"(wp1));
            }
        }
    }

    // epilogue: write to values/mask scratch
#pragma unroll
    for (int i = 0; i < 8; i++) {
        const int row = row0 + ty * 8 + i;
        const int b = row >> 1, s = row & 1;
        float4 o;
        asm("mov.b64 {%0,%1}, %2;" : "=f"(o.x), "=f"(o.y) : "l"(acc0[i]));
        asm("mov.b64 {%0,%1}, %2;" : "=f"(o.z), "=f"(o.w) : "l"(acc1[i]));
        float* dst = (s ? g_mask : g_values) + (size_t)b * H + tx * 4;
        *(float4*)dst = o;
    }
}

// ---------------------------------------------------------------------------
// Kernel B: softmax + contraction.
// out[b,k] = sum_h values[b,h] * exp(mask[b,h]*cov[h,k]) / Z[b,h] + bias[k]
// (logits bounded ~|3| -> no max-subtraction needed; single exp pass)
//
// 256 threads = 8 warps; each warp handles 4 b values.
// Within a warp: lane = g*8 + r ; group g owns row h = h0+g, lane r owns
// k = r*16 + j (j=0..15), exps kept in registers, Z reduced over 8 lanes.
// cov cached in smem, rows padded to 132 floats -> LDS.128 at optimal 4 phases.
// ---------------------------------------------------------------------------
#define CPAD 132

__global__ __launch_bounds__(256, 2)
void head_kernel(const float* __restrict__ cov, const float* __restrict__ bias,
                 float* __restrict__ out)
{
    extern __shared__ float cov_s[];   // [128][CPAD]
    const int tid = threadIdx.x;

    for (int idx = tid; idx < H * H; idx += 256) {
        int h = idx >> 7, k = idx & 127;
        cov_s[h * CPAD + k] = cov[idx];
    }
    __syncthreads();

    const int wid  = tid >> 5;
    const int lane = tid & 31;
    const int g    = lane >> 3;    // 0..3 : which h in the group of 4
    const int r    = lane & 7;     // 0..7 : k chunk r*16..r*16+15

    // bias for this lane's k range (valid for all lanes; used by g==0)
    float4 bias4[4];
#pragma unroll
    for (int jj = 0; jj < 4; jj++)
        bias4[jj] = *(const float4*)(bias + r * 16 + jj * 4);

    const float* crow_base = cov_s + r * 16;

#pragma unroll 1
    for (int i = 0; i < 4; i++) {
        const int b = blockIdx.x * 32 + wid * 4 + i;
        const float* __restrict__ mrow = g_mask   + (size_t)b * H;
        const float* __restrict__ vrow = g_values + (size_t)b * H;

        float acc[16];
#pragma unroll
        for (int j = 0; j < 16; j++) acc[j] = 0.f;

        for (int h0 = 0; h0 < H; h0 += 4) {
            const int h = h0 + g;
            const float tm = __ldg(mrow + h) * 1.4426950408889634f; // log2(e)
            const float* crow = crow_base + h * CPAD;
            float e[16];
            float Z = 0.f;
#pragma unroll
            for (int jj = 0; jj < 4; jj++) {
                float4 c4 = *(const float4*)(crow + jj * 4);
                float e0, e1, e2, e3;
                asm("ex2.approx.ftz.f32 %0, %1;" : "=f"(e0) : "f"(tm * c4.x));
                asm("ex2.approx.ftz.f32 %0, %1;" : "=f"(e1) : "f"(tm * c4.y));
                asm("ex2.approx.ftz.f32 %0, %1;" : "=f"(e2) : "f"(tm * c4.z));
                asm("ex2.approx.ftz.f32 %0, %1;" : "=f"(e3) : "f"(tm * c4.w));
                e[jj*4+0] = e0; e[jj*4+1] = e1; e[jj*4+2] = e2; e[jj*4+3] = e3;
                Z += (e0 + e1) + (e2 + e3);
            }
            // reduce Z over the 8 lanes of this group (xor<8 stays in group)
            Z += __shfl_xor_sync(0xffffffffu, Z, 1);
            Z += __shfl_xor_sync(0xffffffffu, Z, 2);
            Z += __shfl_xor_sync(0xffffffffu, Z, 4);
            const float wgt = __ldg(vrow + h) / Z;
#pragma unroll
            for (int j = 0; j < 16; j++) acc[j] = fmaf(wgt, e[j], acc[j]);
        }

        // cross-group reduction (sum over the 4 h-groups)
#pragma unroll
        for (int j = 0; j < 16; j++) {
            acc[j] += __shfl_xor_sync(0xffffffffu, acc[j], 8);
            acc[j] += __shfl_xor_sync(0xffffffffu, acc[j], 16);
        }
        if (g == 0) {
            float* dst = out + (size_t)b * H + r * 16;
#pragma unroll
            for (int jj = 0; jj < 4; jj++) {
                float4 o;
                o.x = acc[jj*4+0] + bias4[jj].x;
                o.y = acc[jj*4+1] + bias4[jj].y;
                o.z = acc[jj*4+2] + bias4[jj].z;
                o.w = acc[jj*4+3] + bias4[jj].w;
                *(float4*)(dst + jj * 4) = o;
            }
        }
    }
}

// ---------------------------------------------------------------------------
extern "C" void kernel_launch(void* const* d_in, const int* in_sizes, int n_in,
                              void* d_out, int out_size)
{
    (void)n_in; (void)out_size;
    const float* x    = (const float*)d_in[0];   // [B,2,1024]
    const float* W    = (const float*)d_in[1];   // [128,1024]
    const float* cov  = (const float*)d_in[2];   // [128,128]
    const float* bias = (const float*)d_in[3];   // [128]
    float* out = (float*)d_out;

    const int B = in_sizes[0] / (2 * NE);        // 16384

    gemm_vm_kernel<<<(2 * B) / BM, 256>>>(x, W);

    const int smem = H * CPAD * (int)sizeof(float);   // 67584 B
    cudaFuncSetAttribute(head_kernel,
                         cudaFuncAttributeMaxDynamicSharedMemorySize, smem);
    head_kernel<<<B / 32, 256, smem>>>(cov, bias, out);
}

// round 11
// speedup vs baseline: 1.5798x; 1.5798x over previous
#include <cuda_runtime.h>
#include <cuda_bf16.h>
#include <cstdint>

#define NE    1024
#define H     128
#define B_MAX 16384

// ---------------------------------------------------------------------------
// Device scratch (no allocation allowed)
// ---------------------------------------------------------------------------
__device__ float g_values[B_MAX * H];
__device__ float g_mask[B_MAX * H];
// W split into bf16 hi/lo, pre-swizzled SW64 chunk tiles:
// 32 K-chunks, each [128 n-rows x 32 k] bf16 = 128 x 64B = 8192 B.
__device__ unsigned char g_Whi[32 * 8192];
__device__ unsigned char g_Wlo[32 * 8192];

// ---------------------------------------------------------------------------
__device__ __forceinline__ unsigned smem_u32(const void* p) {
    unsigned a;
    asm("{ .reg .u64 t; cvta.to.shared.u64 t, %1; cvt.u32.u64 %0, t; }"
        : "=r"(a) : "l"(p));
    return a;
}
__device__ __host__ __forceinline__ unsigned sw64(unsigned o) {
    return o ^ ((o >> 3) & 0x30);
}

// split fp32x4 -> bf16 hi (packed u64) + bf16 lo (packed u64)
__device__ __forceinline__ void split4(float4 v, unsigned long long& hi,
                                       unsigned long long& lo) {
    __nv_bfloat162 a = __float22bfloat162_rn(make_float2(v.x, v.y));
    __nv_bfloat162 b = __float22bfloat162_rn(make_float2(v.z, v.w));
    float rx = v.x - __bfloat162float(a.x);
    float ry = v.y - __bfloat162float(a.y);
    float rz = v.z - __bfloat162float(b.x);
    float rw = v.w - __bfloat162float(b.y);
    __nv_bfloat162 c = __float22bfloat162_rn(make_float2(rx, ry));
    __nv_bfloat162 d = __float22bfloat162_rn(make_float2(rz, rw));
    unsigned ua = *reinterpret_cast<unsigned*>(&a);
    unsigned ub = *reinterpret_cast<unsigned*>(&b);
    unsigned uc = *reinterpret_cast<unsigned*>(&c);
    unsigned ud = *reinterpret_cast<unsigned*>(&d);
    hi = (unsigned long long)ua | ((unsigned long long)ub << 32);
    lo = (unsigned long long)uc | ((unsigned long long)ud << 32);
}

#define LDMX4(r0, r1, r2, r3, addr)                                          \
    asm volatile("ldmatrix.sync.aligned.m8n8.x4.shared.b16 {%0,%1,%2,%3}, [%4];" \
                 : "=r"(r0), "=r"(r1), "=r"(r2), "=r"(r3) : "r"(addr))

#define MMA16816(c, a0, a1, a2, a3, b0, b1)                                  \
    asm volatile("mma.sync.aligned.m16n8k16.row.col.f32.bf16.bf16.f32 "      \
                 "{%0,%1,%2,%3}, {%4,%5,%6,%7}, {%8,%9}, {%0,%1,%2,%3};"     \
                 : "+f"((c)[0]), "+f"((c)[1]), "+f"((c)[2]), "+f"((c)[3])    \
                 : "r"(a0), "r"(a1), "r"(a2), "r"(a3), "r"(b0), "r"(b1))

#define CP_ASYNC16(dst, src)                                                 \
    asm volatile("cp.async.cg.shared.global [%0], [%1], 16;"                 \
                 :: "r"(dst), "l"(src))

// ---------------------------------------------------------------------------
// Prep: W [128,1024] fp32 -> g_Whi/g_Wlo SW64-swizzled bf16 chunk tiles
// ---------------------------------------------------------------------------
__global__ void prep_w_kernel(const float* __restrict__ W) {
    int idx = blockIdx.x * 256 + threadIdx.x;   // 0..32767
    int h   = idx >> 8;
    int c4g = idx & 255;
    float4 v = *(const float4*)(W + (size_t)h * NE + c4g * 4);
    unsigned long long hi, lo;
    split4(v, hi, lo);
    int kc = c4g >> 3;          // K-chunk (32 wide)
    int c4 = c4g & 7;           // float4 within chunk
    unsigned dst = (unsigned)kc * 8192u + sw64((unsigned)(h * 64 + c4 * 8));
    *reinterpret_cast<unsigned long long*>(g_Whi + dst) = hi;
    *reinterpret_cast<unsigned long long*>(g_Wlo + dst) = lo;
}

// ---------------------------------------------------------------------------
// Tensor-core GEMM via mma.sync (base-ISA; tcgen05 unavailable at sm_103).
// rows = 2B of x [32768,1024] times W^T -> values/mask [B,128].
// CTA: 64 rows x 128 cols, K chunks of 32, double-buffered.
// Split bf16: acc += Ahi*Bhi + Ahi*Blo + Alo*Bhi (fp32 accum).
// SMEM (48KB): Ahi/Alo per stage 4KB each (0..16K), Bhi/Blo 8KB each (16K..48K)
// ---------------------------------------------------------------------------
#define GEMM_SMEM 49152

__global__ __launch_bounds__(256, 2)
void gemm_tc_kernel(const float* __restrict__ x)
{
    extern __shared__ unsigned char sm[];
    const unsigned smb = smem_u32(sm);

    const int tid  = threadIdx.x;
    const int wid  = tid >> 5, lane = tid & 31;
    const int warp_m = wid & 3, warp_n = wid >> 2;
    const int m_base = warp_m * 16, n_base = warp_n * 64;
    const int r0 = blockIdx.x * 64;

    // ---- per-lane ldmatrix offsets (constant across chunks)
    const int lrow8 = (lane & 7) + ((lane >> 3) & 1) * 8;   // row within 16
    const int ksel  = lane >> 4;                             // 0/1 -> k+0 / k+8
    const unsigned aoff0 = sw64((unsigned)((m_base + lrow8) * 64 + ksel * 16));
    const unsigned aoff1 = sw64((unsigned)((m_base + lrow8) * 64 + 32 + ksel * 16));
    unsigned boff[4][2];
#pragma unroll
    for (int p = 0; p < 4; p++) {
        unsigned rb = (unsigned)(n_base + p * 16 + lrow8) * 64 + ksel * 16;
#pragma unroll
        for (int kk = 0; kk < 2; kk++) boff[p][kk] = sw64(rb + kk * 32);
    }

    // ---- x staging map: 2 float4 per thread
    const int xrow = tid >> 3;          // 0..31 (also +32)
    const int xc4  = tid & 7;
    const unsigned asw0 = sw64((unsigned)(xrow * 64 + xc4 * 8));
    const unsigned asw1 = sw64((unsigned)((xrow + 32) * 64 + xc4 * 8));
    const float* xbase = x + (size_t)r0 * NE + xc4 * 4;

    // ---- W cp.async map: 2 x 16B per thread per hi/lo (8KB per chunk)
    const unsigned wdst0 = (unsigned)(tid * 16);
    const unsigned wdst1 = (unsigned)(tid * 16 + 4096);

    float acc[8][4];
#pragma unroll
    for (int t = 0; t < 8; t++)
#pragma unroll
        for (int j = 0; j < 4; j++) acc[t][j] = 0.f;

    // prologue: W chunk 0 via cp.async, x chunk 0 via LDG
    {
        const unsigned char* wh = g_Whi;
        const unsigned char* wl = g_Wlo;
        unsigned bh = smb + 16384, bl = smb + 24576;
        CP_ASYNC16(bh + wdst0, wh + wdst0);
        CP_ASYNC16(bh + wdst1, wh + wdst1);
        CP_ASYNC16(bl + wdst0, wl + wdst0);
        CP_ASYNC16(bl + wdst1, wl + wdst1);
        asm volatile("cp.async.commit_group;");
    }
    float4 xv0 = *(const float4*)(xbase + (size_t)xrow * NE);
    float4 xv1 = *(const float4*)(xbase + (size_t)(xrow + 32) * NE);

    for (int kc = 0; kc < 32; kc++) {
        const int s = kc & 1;
        const unsigned Ahi_b = smb + s * 8192;
        const unsigned Alo_b = Ahi_b + 4096;
        const unsigned Bhi_b = smb + 16384 + s * 16384;
        const unsigned Blo_b = Bhi_b + 8192;

        // ---- stage A (x chunk kc) from prefetched regs, swizzled bf16 hi/lo
        {
            unsigned long long hi, lo;
            split4(xv0, hi, lo);
            *reinterpret_cast<unsigned long long*>(sm + s * 8192 + asw0) = hi;
            *reinterpret_cast<unsigned long long*>(sm + s * 8192 + 4096 + asw0) = lo;
            split4(xv1, hi, lo);
            *reinterpret_cast<unsigned long long*>(sm + s * 8192 + asw1) = hi;
            *reinterpret_cast<unsigned long long*>(sm + s * 8192 + 4096 + asw1) = lo;
        }

        // drain W group for this chunk, then barrier
        asm volatile("cp.async.wait_group 0;");
        __syncthreads();

        // ---- issue next chunk's W + x loads (safe: other buffer's readers done)
        if (kc < 31) {
            const unsigned char* wh = g_Whi + (size_t)(kc + 1) * 8192;
            const unsigned char* wl = g_Wlo + (size_t)(kc + 1) * 8192;
            unsigned bh = smb + 16384 + (s ^ 1) * 16384, bl = bh + 8192;
            CP_ASYNC16(bh + wdst0, wh + wdst0);
            CP_ASYNC16(bh + wdst1, wh + wdst1);
            CP_ASYNC16(bl + wdst0, wl + wdst0);
            CP_ASYNC16(bl + wdst1, wl + wdst1);
            asm volatile("cp.async.commit_group;");
            const float* xs = xbase + (kc + 1) * 32;
            xv0 = *(const float4*)(xs + (size_t)xrow * NE);
            xv1 = *(const float4*)(xs + (size_t)(xrow + 32) * NE);
        }

        // ---- compute: 2 k16 steps
        // ldmatrix.x4 on B tile yields: m0 = n0-7/k0-7, m1 = n8-15/k0-7,
        // m2 = n0-7/k8-15, m3 = n8-15/k8-15. mma B fragment {b0,b1} must be
        // {k0-7, k8-15} of the SAME n octet -> pair (m0,m2) and (m1,m3).
#pragma unroll
        for (int kk = 0; kk < 2; kk++) {
            const unsigned ao = kk ? aoff1 : aoff0;
            unsigned ah0, ah1, ah2, ah3, al0, al1, al2, al3;
            LDMX4(ah0, ah1, ah2, ah3, Ahi_b + ao);
            LDMX4(al0, al1, al2, al3, Alo_b + ao);
#pragma unroll
            for (int p = 0; p < 4; p++) {
                unsigned bh0, bh1, bh2, bh3, bl0, bl1, bl2, bl3;
                LDMX4(bh0, bh1, bh2, bh3, Bhi_b + boff[p][kk]);
                LDMX4(bl0, bl1, bl2, bl3, Blo_b + boff[p][kk]);
                MMA16816(acc[2*p],   ah0, ah1, ah2, ah3, bh0, bh2);
                MMA16816(acc[2*p],   ah0, ah1, ah2, ah3, bl0, bl2);
                MMA16816(acc[2*p],   al0, al1, al2, al3, bh0, bh2);
                MMA16816(acc[2*p+1], ah0, ah1, ah2, ah3, bh1, bh3);
                MMA16816(acc[2*p+1], ah0, ah1, ah2, ah3, bl1, bl3);
                MMA16816(acc[2*p+1], al0, al1, al2, al3, bh1, bh3);
            }
        }
        __syncthreads();   // compute done before next iter's STS into this buffer
    }

    // ---- epilogue: scatter fp32 accums to values/mask scratch
    const int gid = lane >> 2, tig = lane & 3;
    const int row0 = r0 + m_base + gid;
    const int row1 = row0 + 8;
    float* base0 = ((row0 & 1) ? g_mask : g_values) + (size_t)(row0 >> 1) * H;
    float* base1 = ((row1 & 1) ? g_mask : g_values) + (size_t)(row1 >> 1) * H;
#pragma unroll
    for (int nt = 0; nt < 8; nt++) {
        const int col = n_base + nt * 8 + tig * 2;
        *(float2*)(base0 + col) = make_float2(acc[nt][0], acc[nt][1]);
        *(float2*)(base1 + col) = make_float2(acc[nt][2], acc[nt][3]);
    }
}

// ---------------------------------------------------------------------------
// Kernel B: softmax + contraction.
// out[b,k] = sum_h values[b,h] * exp(mask[b,h]*cov[h,k]) / Z[b,h] + bias[k]
// ---------------------------------------------------------------------------
#define CPAD 132

__global__ __launch_bounds__(256, 3)
void head_kernel(const float* __restrict__ cov, const float* __restrict__ bias,
                 float* __restrict__ out)
{
    extern __shared__ float cov_s[];   // [128][CPAD]
    const int tid = threadIdx.x;

    for (int idx = tid; idx < H * H; idx += 256) {
        int h = idx >> 7, k = idx & 127;
        cov_s[h * CPAD + k] = cov[idx];
    }
    __syncthreads();

    const int wid  = tid >> 5;
    const int lane = tid & 31;
    const int g    = lane >> 3;    // h within group of 4
    const int r    = lane & 7;     // k chunk r*16..r*16+15

    const float* crow_base = cov_s + r * 16;

#pragma unroll 1
    for (int i = 0; i < 4; i++) {
        const int b = blockIdx.x * 32 + wid * 4 + i;
        const float* __restrict__ mrow = g_mask   + (size_t)b * H;
        const float* __restrict__ vrow = g_values + (size_t)b * H;

        float acc[16];
#pragma unroll
        for (int j = 0; j < 16; j++) acc[j] = 0.f;

        for (int h0 = 0; h0 < H; h0 += 4) {
            const int h = h0 + g;
            const float tm = __ldg(mrow + h) * 1.4426950408889634f; // log2(e)
            const float* crow = crow_base + h * CPAD;
            float e[16];
            float Z = 0.f;
#pragma unroll
            for (int jj = 0; jj < 4; jj++) {
                float4 c4 = *(const float4*)(crow + jj * 4);
                float e0, e1, e2, e3;
                asm("ex2.approx.ftz.f32 %0, %1;" : "=f"(e0) : "f"(tm * c4.x));
                asm("ex2.approx.ftz.f32 %0, %1;" : "=f"(e1) : "f"(tm * c4.y));
                asm("ex2.approx.ftz.f32 %0, %1;" : "=f"(e2) : "f"(tm * c4.z));
                asm("ex2.approx.ftz.f32 %0, %1;" : "=f"(e3) : "f"(tm * c4.w));
                e[jj*4+0] = e0; e[jj*4+1] = e1; e[jj*4+2] = e2; e[jj*4+3] = e3;
                Z += (e0 + e1) + (e2 + e3);
            }
            Z += __shfl_xor_sync(0xffffffffu, Z, 1);
            Z += __shfl_xor_sync(0xffffffffu, Z, 2);
            Z += __shfl_xor_sync(0xffffffffu, Z, 4);
            const float wgt = __fdividef(__ldg(vrow + h), Z);
#pragma unroll
            for (int j = 0; j < 16; j++) acc[j] = fmaf(wgt, e[j], acc[j]);
        }

#pragma unroll
        for (int j = 0; j < 16; j++) {
            acc[j] += __shfl_xor_sync(0xffffffffu, acc[j], 8);
            acc[j] += __shfl_xor_sync(0xffffffffu, acc[j], 16);
        }
        if (g == 0) {
            float* dst = out + (size_t)b * H + r * 16;
#pragma unroll
            for (int jj = 0; jj < 4; jj++) {
                float4 b4 = *(const float4*)(bias + r * 16 + jj * 4);
                float4 o;
                o.x = acc[jj*4+0] + b4.x;
                o.y = acc[jj*4+1] + b4.y;
                o.z = acc[jj*4+2] + b4.z;
                o.w = acc[jj*4+3] + b4.w;
                *(float4*)(dst + jj * 4) = o;
            }
        }
    }
}

// ---------------------------------------------------------------------------
extern "C" void kernel_launch(void* const* d_in, const int* in_sizes, int n_in,
                              void* d_out, int out_size)
{
    (void)n_in; (void)out_size;
    const float* x    = (const float*)d_in[0];   // [B,2,1024]
    const float* W    = (const float*)d_in[1];   // [128,1024]
    const float* cov  = (const float*)d_in[2];   // [128,128]
    const float* bias = (const float*)d_in[3];   // [128]
    float* out = (float*)d_out;

    const int B = in_sizes[0] / (2 * NE);        // 16384

    prep_w_kernel<<<128, 256>>>(W);

    cudaFuncSetAttribute(gemm_tc_kernel,
                         cudaFuncAttributeMaxDynamicSharedMemorySize, GEMM_SMEM);
    gemm_tc_kernel<<<(2 * B) / 64, 256, GEMM_SMEM>>>(x);

    const int smem = H * CPAD * (int)sizeof(float);   // 67584 B
    cudaFuncSetAttribute(head_kernel,
                         cudaFuncAttributeMaxDynamicSharedMemorySize, smem);
    head_kernel<<<B / 32, 256, smem>>>(cov, bias, out);
}

// round 12
// speedup vs baseline: 2.6109x; 1.6527x over previous
#include <cuda_runtime.h>
#include <cuda_bf16.h>
#include <cstdint>

#define NE    1024
#define H     128
#define B_MAX 16384

// ---------------------------------------------------------------------------
// Device scratch (no allocation allowed)
// W split into bf16 hi/lo, pre-swizzled SW64 chunk tiles:
// 32 K-chunks, each [128 n-rows x 32 k] bf16 = 128 x 64B = 8192 B.
// ---------------------------------------------------------------------------
__device__ __align__(16) unsigned char g_Whi[32 * 8192];
__device__ __align__(16) unsigned char g_Wlo[32 * 8192];

// ---------------------------------------------------------------------------
__device__ __forceinline__ unsigned smem_u32(const void* p) {
    unsigned a;
    asm("{ .reg .u64 t; cvta.to.shared.u64 t, %1; cvt.u32.u64 %0, t; }"
        : "=r"(a) : "l"(p));
    return a;
}
__device__ __host__ __forceinline__ unsigned sw64(unsigned o) {
    return o ^ ((o >> 3) & 0x30);
}

// split fp32x4 -> bf16 hi (packed u64) + bf16 lo (packed u64)
__device__ __forceinline__ void split4(float4 v, unsigned long long& hi,
                                       unsigned long long& lo) {
    __nv_bfloat162 a = __float22bfloat162_rn(make_float2(v.x, v.y));
    __nv_bfloat162 b = __float22bfloat162_rn(make_float2(v.z, v.w));
    float rx = v.x - __bfloat162float(a.x);
    float ry = v.y - __bfloat162float(a.y);
    float rz = v.z - __bfloat162float(b.x);
    float rw = v.w - __bfloat162float(b.y);
    __nv_bfloat162 c = __float22bfloat162_rn(make_float2(rx, ry));
    __nv_bfloat162 d = __float22bfloat162_rn(make_float2(rz, rw));
    unsigned ua = *reinterpret_cast<unsigned*>(&a);
    unsigned ub = *reinterpret_cast<unsigned*>(&b);
    unsigned uc = *reinterpret_cast<unsigned*>(&c);
    unsigned ud = *reinterpret_cast<unsigned*>(&d);
    hi = (unsigned long long)ua | ((unsigned long long)ub << 32);
    lo = (unsigned long long)uc | ((unsigned long long)ud << 32);
}

#define LDMX4(r0, r1, r2, r3, addr)                                          \
    asm volatile("ldmatrix.sync.aligned.m8n8.x4.shared.b16 {%0,%1,%2,%3}, [%4];" \
                 : "=r"(r0), "=r"(r1), "=r"(r2), "=r"(r3) : "r"(addr))

#define MMA16816(c, a0, a1, a2, a3, b0, b1)                                  \
    asm volatile("mma.sync.aligned.m16n8k16.row.col.f32.bf16.bf16.f32 "      \
                 "{%0,%1,%2,%3}, {%4,%5,%6,%7}, {%8,%9}, {%0,%1,%2,%3};"     \
                 : "+f"((c)[0]), "+f"((c)[1]), "+f"((c)[2]), "+f"((c)[3])    \
                 : "r"(a0), "r"(a1), "r"(a2), "r"(a3), "r"(b0), "r"(b1))

#define CP_ASYNC16(dst, src)                                                 \
    asm volatile("cp.async.cg.shared.global [%0], [%1], 16;"                 \
                 :: "r"(dst), "l"(src))

// ---------------------------------------------------------------------------
// Prep: W [128,1024] fp32 -> g_Whi/g_Wlo SW64-swizzled bf16 chunk tiles
// ---------------------------------------------------------------------------
__global__ void prep_w_kernel(const float* __restrict__ W) {
    int idx = blockIdx.x * 256 + threadIdx.x;   // 0..32767
    int h   = idx >> 8;
    int c4g = idx & 255;
    float4 v = *(const float4*)(W + (size_t)h * NE + c4g * 4);
    unsigned long long hi, lo;
    split4(v, hi, lo);
    int kc = c4g >> 3;          // K-chunk (32 wide)
    int c4 = c4g & 7;           // float4 within chunk
    unsigned dst = (unsigned)kc * 8192u + sw64((unsigned)(h * 64 + c4 * 8));
    *reinterpret_cast<unsigned long long*>(g_Whi + dst) = hi;
    *reinterpret_cast<unsigned long long*>(g_Wlo + dst) = lo;
}

// ---------------------------------------------------------------------------
// Fused kernel.
// Phase 1 (GEMM): 64 rows (= 32 b x {values,mask}) x 128 cols via mma.sync,
//   split bf16 (acc += Ahi*Bhi + Ahi*Blo + Alo*Bhi), K chunks of 32,
//   double-buffered cp.async for W, LDG->split->swizzled STS for x.
// Phase 2 (head): same CTA consumes its 32 b's from smem:
//   out[b,k] = sum_h values[b,h] * exp(mask[b,h]*cov[h,k]) / Z[b,h] + bias[k]
//   (logits bounded ~|3| -> single exp pass, no max subtraction)
//   cov cached fp32 in smem [128][128]; conflict-free k-map: lane r owns
//   k = w*32 + r*4 + t (each 8-lane phase reads 32 consecutive floats).
//
// SMEM (bytes):
//   [0, 49152)      gemm staging (A: 2 stages x 8KB, B: 2 stages x 16KB)
//   [0, 33792)      reused after mainloop as vm[64][132] fp32
//   [33792, 99328)  cov fp32 [128][128]
// ---------------------------------------------------------------------------
#define FUSED_SMEM 99328
#define VM_PAD 132

__global__ __launch_bounds__(256, 2)
void fused_kernel(const float* __restrict__ x, const float* __restrict__ cov,
                  const float* __restrict__ bias, float* __restrict__ out)
{
    extern __shared__ unsigned char sm[];
    float* smf = reinterpret_cast<float*>(sm);
    const unsigned smb = smem_u32(sm);

    const int tid  = threadIdx.x;
    const int wid  = tid >> 5, lane = tid & 31;
    const int warp_m = wid & 3, warp_n = wid >> 2;
    const int m_base = warp_m * 16, n_base = warp_n * 64;
    const int r0 = blockIdx.x * 64;

    // ---- per-lane ldmatrix offsets
    const int lrow8 = (lane & 7) + ((lane >> 3) & 1) * 8;
    const int ksel  = lane >> 4;
    const unsigned aoff0 = sw64((unsigned)((m_base + lrow8) * 64 + ksel * 16));
    const unsigned aoff1 = sw64((unsigned)((m_base + lrow8) * 64 + 32 + ksel * 16));
    unsigned boff[4][2];
#pragma unroll
    for (int p = 0; p < 4; p++) {
        unsigned rb = (unsigned)(n_base + p * 16 + lrow8) * 64 + ksel * 16;
#pragma unroll
        for (int kk = 0; kk < 2; kk++) boff[p][kk] = sw64(rb + kk * 32);
    }

    // ---- x staging map: 2 float4 per thread
    const int xrow = tid >> 3;
    const int xc4  = tid & 7;
    const unsigned asw0 = sw64((unsigned)(xrow * 64 + xc4 * 8));
    const unsigned asw1 = sw64((unsigned)((xrow + 32) * 64 + xc4 * 8));
    const float* xbase = x + (size_t)r0 * NE + xc4 * 4;

    // ---- W cp.async map
    const unsigned wdst0 = (unsigned)(tid * 16);
    const unsigned wdst1 = (unsigned)(tid * 16 + 4096);

    float acc[8][4];
#pragma unroll
    for (int t = 0; t < 8; t++)
#pragma unroll
        for (int j = 0; j < 4; j++) acc[t][j] = 0.f;

    // prologue
    {
        unsigned bh = smb + 16384, bl = smb + 24576;
        CP_ASYNC16(bh + wdst0, g_Whi + wdst0);
        CP_ASYNC16(bh + wdst1, g_Whi + wdst1);
        CP_ASYNC16(bl + wdst0, g_Wlo + wdst0);
        CP_ASYNC16(bl + wdst1, g_Wlo + wdst1);
        asm volatile("cp.async.commit_group;");
    }
    float4 xv0 = *(const float4*)(xbase + (size_t)xrow * NE);
    float4 xv1 = *(const float4*)(xbase + (size_t)(xrow + 32) * NE);

    for (int kc = 0; kc < 32; kc++) {
        const int s = kc & 1;
        const unsigned Ahi_b = smb + s * 8192;
        const unsigned Alo_b = Ahi_b + 4096;
        const unsigned Bhi_b = smb + 16384 + s * 16384;
        const unsigned Blo_b = Bhi_b + 8192;

        {
            unsigned long long hi, lo;
            split4(xv0, hi, lo);
            *reinterpret_cast<unsigned long long*>(sm + s * 8192 + asw0) = hi;
            *reinterpret_cast<unsigned long long*>(sm + s * 8192 + 4096 + asw0) = lo;
            split4(xv1, hi, lo);
            *reinterpret_cast<unsigned long long*>(sm + s * 8192 + asw1) = hi;
            *reinterpret_cast<unsigned long long*>(sm + s * 8192 + 4096 + asw1) = lo;
        }

        asm volatile("cp.async.wait_group 0;");
        __syncthreads();

        if (kc < 31) {
            const unsigned char* wh = g_Whi + (size_t)(kc + 1) * 8192;
            const unsigned char* wl = g_Wlo + (size_t)(kc + 1) * 8192;
            unsigned bh = smb + 16384 + (s ^ 1) * 16384, bl = bh + 8192;
            CP_ASYNC16(bh + wdst0, wh + wdst0);
            CP_ASYNC16(bh + wdst1, wh + wdst1);
            CP_ASYNC16(bl + wdst0, wl + wdst0);
            CP_ASYNC16(bl + wdst1, wl + wdst1);
            asm volatile("cp.async.commit_group;");
            const float* xs = xbase + (kc + 1) * 32;
            xv0 = *(const float4*)(xs + (size_t)xrow * NE);
            xv1 = *(const float4*)(xs + (size_t)(xrow + 32) * NE);
        }

        // ldmatrix.x4 on B: m0=n0-7/k0-7, m1=n8-15/k0-7, m2=n0-7/k8-15,
        // m3=n8-15/k8-15 -> mma B pairs (m0,m2) and (m1,m3).
#pragma unroll
        for (int kk = 0; kk < 2; kk++) {
            const unsigned ao = kk ? aoff1 : aoff0;
            unsigned ah0, ah1, ah2, ah3, al0, al1, al2, al3;
            LDMX4(ah0, ah1, ah2, ah3, Ahi_b + ao);
            LDMX4(al0, al1, al2, al3, Alo_b + ao);
#pragma unroll
            for (int p = 0; p < 4; p++) {
                unsigned bh0, bh1, bh2, bh3, bl0, bl1, bl2, bl3;
                LDMX4(bh0, bh1, bh2, bh3, Bhi_b + boff[p][kk]);
                LDMX4(bl0, bl1, bl2, bl3, Blo_b + boff[p][kk]);
                MMA16816(acc[2*p],   ah0, ah1, ah2, ah3, bh0, bh2);
                MMA16816(acc[2*p],   ah0, ah1, ah2, ah3, bl0, bl2);
                MMA16816(acc[2*p],   al0, al1, al2, al3, bh0, bh2);
                MMA16816(acc[2*p+1], ah0, ah1, ah2, ah3, bh1, bh3);
                MMA16816(acc[2*p+1], ah0, ah1, ah2, ah3, bl1, bl3);
                MMA16816(acc[2*p+1], al0, al1, al2, al3, bh1, bh3);
            }
        }
        __syncthreads();
    }

    // ---- epilogue: accums -> vm_s[64][VM_PAD] fp32 (rows: m=2*b_local+s)
    {
        const int gid = lane >> 2, tig = lane & 3;
        const int m0 = m_base + gid, m1 = m0 + 8;
#pragma unroll
        for (int nt = 0; nt < 8; nt++) {
            const int col = n_base + nt * 8 + tig * 2;
            *(float2*)(smf + m0 * VM_PAD + col) = make_float2(acc[nt][0], acc[nt][1]);
            *(float2*)(smf + m1 * VM_PAD + col) = make_float2(acc[nt][2], acc[nt][3]);
        }
    }
    __syncthreads();

    // ---- load cov fp32 [128][128] into smem (region disjoint from vm_s)
    {
        const float4* cg = (const float4*)cov;
        float4* cs = (float4*)(smf + 64 * VM_PAD);   // 8448 floats in
#pragma unroll 4
        for (int i = tid; i < (H * H) / 4; i += 256)
            cs[i] = cg[i];
    }
    __syncthreads();

    // ---- head phase: 8 warps x 4 b each (32 b per CTA)
    const float* cov_s = smf + 64 * VM_PAD;
    const int g = lane >> 3;      // h within group of 4
    const int r = lane & 7;       // lane owns k = w*32 + r*4 + t
    const float* crow_base = cov_s + r * 4;

#pragma unroll 1
    for (int i = 0; i < 4; i++) {
        const int bl = wid * 4 + i;
        const float* vrow = smf + (2 * bl) * VM_PAD;       // values row
        const float* mrow = smf + (2 * bl + 1) * VM_PAD;   // mask row

        float oacc[16];
#pragma unroll
        for (int j = 0; j < 16; j++) oacc[j] = 0.f;

        for (int h0 = 0; h0 < H; h0 += 4) {
            const int h = h0 + g;
            const float tm = mrow[h] * 1.4426950408889634f;   // log2(e)
            const float* crow = crow_base + h * H;
            float e[16];
            float Z = 0.f;
#pragma unroll
            for (int w = 0; w < 4; w++) {
                float4 c4 = *(const float4*)(crow + w * 32);
                float e0, e1, e2, e3;
                asm("ex2.approx.ftz.f32 %0, %1;" : "=f"(e0) : "f"(tm * c4.x));
                asm("ex2.approx.ftz.f32 %0, %1;" : "=f"(e1) : "f"(tm * c4.y));
                asm("ex2.approx.ftz.f32 %0, %1;" : "=f"(e2) : "f"(tm * c4.z));
                asm("ex2.approx.ftz.f32 %0, %1;" : "=f"(e3) : "f"(tm * c4.w));
                e[w*4+0] = e0; e[w*4+1] = e1; e[w*4+2] = e2; e[w*4+3] = e3;
                Z += (e0 + e1) + (e2 + e3);
            }
            Z += __shfl_xor_sync(0xffffffffu, Z, 1);
            Z += __shfl_xor_sync(0xffffffffu, Z, 2);
            Z += __shfl_xor_sync(0xffffffffu, Z, 4);
            const float wgt = __fdividef(vrow[h], Z);
#pragma unroll
            for (int j = 0; j < 16; j++) oacc[j] = fmaf(wgt, e[j], oacc[j]);
        }

#pragma unroll
        for (int j = 0; j < 16; j++) {
            oacc[j] += __shfl_xor_sync(0xffffffffu, oacc[j], 8);
            oacc[j] += __shfl_xor_sync(0xffffffffu, oacc[j], 16);
        }
        if (g == 0) {
            const int b = blockIdx.x * 32 + bl;
            float* dst = out + (size_t)b * H + r * 4;
#pragma unroll
            for (int w = 0; w < 4; w++) {
                float4 b4 = *(const float4*)(bias + w * 32 + r * 4);
                float4 o;
                o.x = oacc[w*4+0] + b4.x;
                o.y = oacc[w*4+1] + b4.y;
                o.z = oacc[w*4+2] + b4.z;
                o.w = oacc[w*4+3] + b4.w;
                *(float4*)(dst + w * 32) = o;
            }
        }
    }
}

// ---------------------------------------------------------------------------
extern "C" void kernel_launch(void* const* d_in, const int* in_sizes, int n_in,
                              void* d_out, int out_size)
{
    (void)n_in; (void)out_size;
    const float* x    = (const float*)d_in[0];   // [B,2,1024]
    const float* W    = (const float*)d_in[1];   // [128,1024]
    const float* cov  = (const float*)d_in[2];   // [128,128]
    const float* bias = (const float*)d_in[3];   // [128]
    float* out = (float*)d_out;

    const int B = in_sizes[0] / (2 * NE);        // 16384

    prep_w_kernel<<<128, 256>>>(W);

    cudaFuncSetAttribute(fused_kernel,
                         cudaFuncAttributeMaxDynamicSharedMemorySize, FUSED_SMEM);
    fused_kernel<<<(2 * B) / 64, 256, FUSED_SMEM>>>(x, cov, bias, out);
}